// round 2
// baseline (speedup 1.0000x reference)
#include <cuda_runtime.h>
#include <cuda_bf16.h>
#include <math.h>

// Problem constants
#define BB 128
#define LL 256
#define NN 8
#define FF 200
#define F3 600
#define AOUT 39
#define BOUT 10
#define BL (BB*LL)           // 32768
#define RROUNDS 2            // R-1
#define TSTEPS 2

// ------------------------- scratch (device globals) -------------------------
__device__ float g_h[BL*FF];
__device__ float g_act[BL*FF];
__device__ float g_ctx[BL*FF];
__device__ float g_gi[BL*F3];
__device__ float g_gh[BL*F3];
__device__ float g_s1[BL*FF];
__device__ float g_s2[BL*FF];
__device__ float g_t[BL*FF];
__device__ float g_molW[BB*FF];
__device__ float g_al[BL*AOUT];
__device__ float g_u1[BL*BOUT];
__device__ float g_u2[BL*BOUT];

// ------------------------- SGEMM 128x128x8, 8x8 microtile --------------------
// C[M,N] = act(A[M,K] @ W[N,K]^T + bias + rowAdd), K % 8 == 0, M % 128 == 0.
// ACT: 0 none, 1 elu, 2 relu
template<int ACT>
__global__ __launch_bounds__(256, 2) void gemm_nt(
    const float* __restrict__ A, const float* __restrict__ W,
    const float* __restrict__ bias, float* __restrict__ C,
    int M, int N, int K, int ldw,
    const float* __restrict__ rowAdd, int rowsPerGroup)
{
    __shared__ float As[2][8][132];
    __shared__ float Bs[2][8][132];

    const int bm = blockIdx.y * 128;
    const int bn = blockIdx.x * 128;
    const int tid = threadIdx.x;
    const int tx = tid & 15;        // n dim
    const int ty = tid >> 4;        // m dim

    // G2S loader mapping: each thread loads one float4 of A and one of B per tile
    const int lr = tid >> 1;              // row within 128-tile
    const int lc = (tid & 1) * 4;         // k offset within 8

    const float* Aptr = A + (size_t)(bm + lr) * K + lc;
    const int wn = bn + lr;
    const bool wok = (wn < N);
    const float* Wptr = wok ? (W + (size_t)wn * ldw + lc) : W;

    float acc[8][8];
    #pragma unroll
    for (int i = 0; i < 8; i++)
        #pragma unroll
        for (int j = 0; j < 8; j++) acc[i][j] = 0.f;

    const int ntiles = K >> 3;

    // preload tile 0
    {
        float4 a4 = *(const float4*)Aptr;
        float4 b4 = wok ? *(const float4*)Wptr : make_float4(0.f, 0.f, 0.f, 0.f);
        As[0][lc + 0][lr] = a4.x; As[0][lc + 1][lr] = a4.y;
        As[0][lc + 2][lr] = a4.z; As[0][lc + 3][lr] = a4.w;
        Bs[0][lc + 0][lr] = b4.x; Bs[0][lc + 1][lr] = b4.y;
        Bs[0][lc + 2][lr] = b4.z; Bs[0][lc + 3][lr] = b4.w;
    }
    __syncthreads();

    for (int t = 0; t < ntiles; t++) {
        const int cur = t & 1, nxt = cur ^ 1;
        float4 a4, b4;
        const bool more = (t + 1 < ntiles);
        if (more) {
            a4 = *(const float4*)(Aptr + (t + 1) * 8);
            b4 = wok ? *(const float4*)(Wptr + (t + 1) * 8)
                     : make_float4(0.f, 0.f, 0.f, 0.f);
        }

        #pragma unroll
        for (int kk = 0; kk < 8; kk++) {
            float4 af0 = *(const float4*)&As[cur][kk][ty * 8];
            float4 af1 = *(const float4*)&As[cur][kk][ty * 8 + 4];
            float4 bf0 = *(const float4*)&Bs[cur][kk][tx * 8];
            float4 bf1 = *(const float4*)&Bs[cur][kk][tx * 8 + 4];
            float a[8] = {af0.x, af0.y, af0.z, af0.w, af1.x, af1.y, af1.z, af1.w};
            float b[8] = {bf0.x, bf0.y, bf0.z, bf0.w, bf1.x, bf1.y, bf1.z, bf1.w};
            #pragma unroll
            for (int i = 0; i < 8; i++)
                #pragma unroll
                for (int j = 0; j < 8; j++)
                    acc[i][j] += a[i] * b[j];
        }

        if (more) {
            As[nxt][lc + 0][lr] = a4.x; As[nxt][lc + 1][lr] = a4.y;
            As[nxt][lc + 2][lr] = a4.z; As[nxt][lc + 3][lr] = a4.w;
            Bs[nxt][lc + 0][lr] = b4.x; Bs[nxt][lc + 1][lr] = b4.y;
            Bs[nxt][lc + 2][lr] = b4.z; Bs[nxt][lc + 3][lr] = b4.w;
            __syncthreads();
        }
    }

    #pragma unroll
    for (int i = 0; i < 8; i++) {
        int m = bm + ty * 8 + i;
        const float* ra = rowAdd ? (rowAdd + (size_t)(m / rowsPerGroup) * N) : nullptr;
        float* crow = C + (size_t)m * N;
        #pragma unroll
        for (int j = 0; j < 8; j++) {
            int n = bn + tx * 8 + j;
            if (n >= N) continue;
            float v = acc[i][j];
            if (bias) v += bias[n];
            if (ra) v += ra[n];
            if (ACT == 1) v = (v > 0.f) ? v : expm1f(v);
            else if (ACT == 2) v = fmaxf(v, 0.f);
            crow[n] = v;
        }
    }
}

// ------------------------- mol phase init ------------------------------------
__global__ __launch_bounds__(256) void mol_pre_kernel(
    const float* __restrict__ molf, const float* __restrict__ actf,
    float* __restrict__ h0)
{
    int b = blockIdx.x;
    int tid = threadIdx.x;
    __shared__ float dots[LL];
    __shared__ float red[16];
    const float* mf = molf + (size_t)b * FF;
    int lane = tid & 31, warp = tid >> 5;

    for (int l = warp; l < LL; l += 8) {
        const float* af = actf + ((size_t)b * LL + l) * FF;
        float s = 0.f;
        for (int f = lane; f < FF; f += 32) s += mf[f] * af[f];
        #pragma unroll
        for (int o = 16; o > 0; o >>= 1) s += __shfl_xor_sync(0xffffffffu, s, o);
        if (lane == 0) dots[l] = s;
    }
    __syncthreads();

    float v = dots[tid];
    float m = v;
    #pragma unroll
    for (int o = 16; o > 0; o >>= 1) m = fmaxf(m, __shfl_xor_sync(0xffffffffu, m, o));
    if (lane == 0) red[warp] = m;
    __syncthreads();
    float mx = red[0];
    #pragma unroll
    for (int i = 1; i < 8; i++) mx = fmaxf(mx, red[i]);
    float e = expf(v - mx);
    float s = e;
    #pragma unroll
    for (int o = 16; o > 0; o >>= 1) s += __shfl_xor_sync(0xffffffffu, s, o);
    if (lane == 0) red[8 + warp] = s;
    __syncthreads();
    float tot = 0.f;
    #pragma unroll
    for (int i = 0; i < 8; i++) tot += red[8 + i];
    __syncthreads();
    dots[tid] = e / tot;
    __syncthreads();

    size_t base = (size_t)b * LL * FF;
    for (int i = tid; i < LL * FF; i += 256) {
        int l = i / FF, f = i - l * FF;
        h0[base + i] = dots[l] * mf[f] + actf[base + i];
    }
}

// ------------------------- GRU gate combine ----------------------------------
__global__ __launch_bounds__(256) void gru_combine_kernel(
    const float* __restrict__ gi, const float* __restrict__ gh,
    const float* __restrict__ hin, float* __restrict__ hout,
    float* __restrict__ actout, int total)
{
    int idx = blockIdx.x * blockDim.x + threadIdx.x;
    if (idx >= total) return;
    int m = idx / FF, f = idx - m * FF;
    size_t b3 = (size_t)m * F3;
    float ir = gi[b3 + f], iz = gi[b3 + FF + f], in_ = gi[b3 + 2 * FF + f];
    float hr = gh[b3 + f], hz = gh[b3 + FF + f], hn = gh[b3 + 2 * FF + f];
    float r = 1.f / (1.f + expf(-(ir + hr)));
    float z = 1.f / (1.f + expf(-(iz + hz)));
    float n = tanhf(in_ + r * hn);
    float h = hin[idx];
    float o = (1.f - z) * n + z * h;
    if (hout) hout[idx] = o;
    actout[idx] = fmaxf(o, 0.f);
}

// ------------------------- neighbor attention context ------------------------
__global__ __launch_bounds__(256) void attn_ctx_kernel(
    const float* __restrict__ s1, const float* __restrict__ s2,
    const float* __restrict__ tt, const int* __restrict__ deg,
    float* __restrict__ ctx)
{
    int bl = blockIdx.x;
    int b = bl >> 8;           // L = 256
    int tid = threadIdx.x;
    __shared__ int sidx[NN];
    if (tid < NN) sidx[tid] = deg[(size_t)bl * NN + tid];
    __syncthreads();
    if (tid >= FF) return;
    int f = tid;
    float s1v = s1[(size_t)bl * FF + f];
    float sc[NN];
    float mx = -3.4e38f;
    #pragma unroll
    for (int n = 0; n < NN; n++) {
        int j = sidx[n];
        float v = s1v + s2[((size_t)b * LL + j) * FF + f];
        v = (v >= 0.f) ? v : 0.01f * v;          // leaky_relu(0.01)
        if (j == LL - 1) v += -9e8f;              // softmax mask
        sc[n] = v;
        mx = fmaxf(mx, v);
    }
    float sum = 0.f;
    #pragma unroll
    for (int n = 0; n < NN; n++) { sc[n] = expf(sc[n] - mx); sum += sc[n]; }
    float inv = 1.f / sum;
    float c = 0.f;
    #pragma unroll
    for (int n = 0; n < NN; n++) {
        int j = sidx[n];
        if (j != LL - 1)
            c += sc[n] * inv * tt[((size_t)b * LL + j) * FF + f];
    }
    c = (c > 0.f) ? c : expm1f(c);                // elu
    ctx[(size_t)bl * FF + f] = c;
}

// ------------------------- decoders ------------------------------------------
__device__ __forceinline__ void seg_softmax_acc(const float* v, float* y, int lo, int hi) {
    float m = -3.4e38f;
    for (int i = lo; i < hi; i++) m = fmaxf(m, v[i]);
    float s = 0.f;
    for (int i = lo; i < hi; i++) s += expf(v[i] - m);
    float inv = 1.f / s;
    for (int i = lo; i < hi; i++) y[i] += expf(v[i] - m) * inv;
}
__device__ __forceinline__ float sigf(float x) { return 1.f / (1.f + expf(-x)); }

__global__ __launch_bounds__(256) void atom_act_kernel(
    const float* __restrict__ al, float* __restrict__ out, int rows)
{
    int m = blockIdx.x * blockDim.x + threadIdx.x;
    if (m >= rows) return;
    const float* x = al + (size_t)m * AOUT;
    float v[AOUT], y[AOUT];
    #pragma unroll
    for (int i = 0; i < AOUT; i++) { v[i] = x[i]; y[i] = 0.f; }
    seg_softmax_acc(v, y, 0, 16);
    seg_softmax_acc(v, y, 16, 22);
    seg_softmax_acc(v, y, 24, 30);
    seg_softmax_acc(v, y, 31, 36);
    y[24] += fmaxf(v[24], 0.f);
    y[30] += sigf(v[30]);
    y[36] += sigf(v[36]);
    y[37] += sigf(v[37]);
    y[38] += sigf(v[38]);
    float* o = out + (size_t)m * AOUT;
    #pragma unroll
    for (int i = 0; i < AOUT; i++) o[i] = y[i];
}

__global__ __launch_bounds__(256) void bond_act_kernel(
    const float* __restrict__ u1, const float* __restrict__ u2,
    const int* __restrict__ deg, float* __restrict__ out, int total)
{
    int id = blockIdx.x * blockDim.x + threadIdx.x;
    if (id >= total) return;                      // total = BL*NN
    int bl = id / NN;
    int b = bl >> 8;
    int j = deg[id];
    const float* a = u1 + (size_t)bl * BOUT;
    const float* c = u2 + ((size_t)b * LL + j) * BOUT;
    float v[BOUT], y[BOUT];
    #pragma unroll
    for (int k = 0; k < BOUT; k++) { v[k] = a[k] + c[k]; y[k] = 0.f; }
    seg_softmax_acc(v, y, 0, 4);
    seg_softmax_acc(v, y, 6, 10);
    y[4] += sigf(v[4]);
    y[5] += sigf(v[5]);
    float* o = out + (size_t)id * BOUT;
    #pragma unroll
    for (int k = 0; k < BOUT; k++) o[k] = y[k];
}

// ------------------------- host orchestration --------------------------------
static inline dim3 gemm_grid(int M, int N) {
    return dim3((N + 127) / 128, (M + 127) / 128);
}

extern "C" void kernel_launch(void* const* d_in, const int* in_sizes, int n_in,
                              void* d_out, int out_size)
{
    const int*   deg        = (const int*)  d_in[2];
    const float* molf       = (const float*)d_in[5];
    const float* actf       = (const float*)d_in[6];
    const float* atom_fc_w  = (const float*)d_in[7];
    const float* atom_fc_b  = (const float*)d_in[8];
    const float* bond_fc_w  = (const float*)d_in[9];
    const float* bond_fc_b  = (const float*)d_in[10];
    const float* align_w    = (const float*)d_in[11];
    const float* align_b    = (const float*)d_in[12];
    const float* attend_w   = (const float*)d_in[13];
    const float* attend_b   = (const float*)d_in[14];
    const float* gru_wih    = (const float*)d_in[15];
    const float* gru_whh    = (const float*)d_in[16];
    const float* gru_bih    = (const float*)d_in[17];
    const float* gru_bhh    = (const float*)d_in[18];
    const float* mol_al_w   = (const float*)d_in[19];
    const float* mol_al_b   = (const float*)d_in[20];
    const float* mgru_wih   = (const float*)d_in[21];
    const float* mgru_whh   = (const float*)d_in[22];
    const float* mgru_bih   = (const float*)d_in[23];
    const float* mgru_bhh   = (const float*)d_in[24];
    float* out = (float*)d_out;

    float *p_h, *p_act, *p_ctx, *p_gi, *p_gh, *p_s1, *p_s2, *p_t, *p_molW, *p_al, *p_u1, *p_u2;
    cudaGetSymbolAddress((void**)&p_h,    g_h);
    cudaGetSymbolAddress((void**)&p_act,  g_act);
    cudaGetSymbolAddress((void**)&p_ctx,  g_ctx);
    cudaGetSymbolAddress((void**)&p_gi,   g_gi);
    cudaGetSymbolAddress((void**)&p_gh,   g_gh);
    cudaGetSymbolAddress((void**)&p_s1,   g_s1);
    cudaGetSymbolAddress((void**)&p_s2,   g_s2);
    cudaGetSymbolAddress((void**)&p_t,    g_t);
    cudaGetSymbolAddress((void**)&p_molW, g_molW);
    cudaGetSymbolAddress((void**)&p_al,   g_al);
    cudaGetSymbolAddress((void**)&p_u1,   g_u1);
    cudaGetSymbolAddress((void**)&p_u2,   g_u2);

    // 1) mol phase init: g_h = git0
    mol_pre_kernel<<<BB, 256>>>(molf, actf, p_h);

    // 2) molW = mol_feature @ Wm[:, :F]^T + mol_align_b   (constant over t)
    gemm_nt<0><<<gemm_grid(BB, FF), 256>>>(molf, mol_al_w, mol_al_b, p_molW,
                                           BB, FF, FF, 2 * FF, nullptr, 1);

    // 3) T GRU steps on mol features
    for (int t = 0; t < TSTEPS; t++) {
        gemm_nt<1><<<gemm_grid(BL, FF), 256>>>(p_h, mol_al_w + FF, nullptr, p_ctx,
                                               BL, FF, FF, 2 * FF, p_molW, LL);
        gemm_nt<0><<<gemm_grid(BL, F3), 256>>>(p_ctx, mgru_wih, mgru_bih, p_gi,
                                               BL, F3, FF, FF, nullptr, 1);
        gemm_nt<0><<<gemm_grid(BL, F3), 256>>>(p_h, mgru_whh, mgru_bhh, p_gh,
                                               BL, F3, FF, FF, nullptr, 1);
        gru_combine_kernel<<<(BL * FF + 255) / 256, 256>>>(p_gi, p_gh, p_h, p_h, p_act, BL * FF);
    }

    // 4) R-1 rounds of neighbor attention + GRU
    for (int d = 0; d < RROUNDS; d++) {
        const float* aw = align_w + (size_t)d * FF * 2 * FF;
        gemm_nt<0><<<gemm_grid(BL, FF), 256>>>(p_act, aw, align_b + (size_t)d * FF, p_s1,
                                               BL, FF, FF, 2 * FF, nullptr, 1);
        gemm_nt<0><<<gemm_grid(BL, FF), 256>>>(p_act, aw + FF, nullptr, p_s2,
                                               BL, FF, FF, 2 * FF, nullptr, 1);
        gemm_nt<0><<<gemm_grid(BL, FF), 256>>>(p_act, attend_w + (size_t)d * FF * FF,
                                               attend_b + (size_t)d * FF, p_t,
                                               BL, FF, FF, FF, nullptr, 1);
        attn_ctx_kernel<<<BL, 256>>>(p_s1, p_s2, p_t, deg, p_ctx);
        gemm_nt<0><<<gemm_grid(BL, F3), 256>>>(p_ctx, gru_wih + (size_t)d * F3 * FF,
                                               gru_bih + (size_t)d * F3, p_gi,
                                               BL, F3, FF, FF, nullptr, 1);
        gemm_nt<0><<<gemm_grid(BL, F3), 256>>>(p_act, gru_whh + (size_t)d * F3 * FF,
                                               gru_bhh + (size_t)d * F3, p_gh,
                                               BL, F3, FF, FF, nullptr, 1);
        gru_combine_kernel<<<(BL * FF + 255) / 256, 256>>>(p_gi, p_gh, p_act, nullptr, p_act, BL * FF);
    }

    // 5) decode
    gemm_nt<0><<<gemm_grid(BL, AOUT), 256>>>(p_act, atom_fc_w, atom_fc_b, p_al,
                                             BL, AOUT, FF, FF, nullptr, 1);
    gemm_nt<0><<<gemm_grid(BL, BOUT), 256>>>(p_act, bond_fc_w, bond_fc_b, p_u1,
                                             BL, BOUT, FF, 2 * FF, nullptr, 1);
    gemm_nt<0><<<gemm_grid(BL, BOUT), 256>>>(p_act, bond_fc_w + FF, nullptr, p_u2,
                                             BL, BOUT, FF, 2 * FF, nullptr, 1);

    atom_act_kernel<<<(BL + 255) / 256, 256>>>(p_al, out, BL);
    bond_act_kernel<<<(BL * NN + 255) / 256, 256>>>(p_u1, p_u2, deg,
                                                    out + (size_t)BL * AOUT, BL * NN);
}

// round 5
// speedup vs baseline: 1.2848x; 1.2848x over previous
#include <cuda_runtime.h>
#include <cuda_bf16.h>
#include <math.h>
#include <stdint.h>

// Problem constants
#define BB 128
#define LL 256
#define NNB 8
#define FF 200
#define F3 600
#define BL (BB*LL)           // 32768
#define RROUNDS 2
#define TSTEPS 2
#define KPAD 224
#define NCH 7                // 224/32 k-chunks

// ------------------------- scratch (device globals) -------------------------
__device__ float g_h[BL*FF];
__device__ float g_act[BL*FF];
__device__ float g_ctx[BL*FF];
__device__ float g_gi[BL*F3];
__device__ float g_gh[BL*F3];
__device__ float g_s1[BL*FF];
__device__ float g_s2[BL*FF];
__device__ float g_t[BL*FF];
__device__ float g_molW[BB*FF];
__device__ float g_dec[BL*64];
__device__ float g_decb[64];

// packed split-bf16 weight planes [row][KPAD]
#define WROWS 5264
__device__ __align__(16) __nv_bfloat16 g_whi[WROWS*KPAD];
__device__ __align__(16) __nv_bfloat16 g_wlo[WROWS*KPAD];

// weight row offsets
#define W_MOL0 0
#define W_MOL1 200
#define W_MGI  400
#define W_MGH  1000
#define W_RND(d) (1600 + (d)*1800)   // +0 aln0, +200 aln1, +400 att, +600 gwi, +1200 gwh
#define W_DEC  5200

// ------------------------- helpers -------------------------------------------
__device__ __forceinline__ uint32_t smem_u32(const void* p) {
    uint32_t a;
    asm("{ .reg .u64 t; cvta.to.shared.u64 t, %1; cvt.u32.u64 %0, t; }"
        : "=r"(a) : "l"(p));
    return a;
}
__device__ __forceinline__ void ldsm4(uint32_t* r, uint32_t a) {
    asm volatile("ldmatrix.sync.aligned.m8n8.x4.shared.b16 {%0,%1,%2,%3}, [%4];"
        : "=r"(r[0]), "=r"(r[1]), "=r"(r[2]), "=r"(r[3]) : "r"(a));
}
__device__ __forceinline__ void mma_bf16(float* c, const uint32_t* a, const uint32_t* b) {
    asm volatile("mma.sync.aligned.m16n8k16.row.col.f32.bf16.bf16.f32 "
        "{%0,%1,%2,%3}, {%4,%5,%6,%7}, {%8,%9}, {%0,%1,%2,%3};"
        : "+f"(c[0]), "+f"(c[1]), "+f"(c[2]), "+f"(c[3])
        : "r"(a[0]), "r"(a[1]), "r"(a[2]), "r"(a[3]), "r"(b[0]), "r"(b[1]));
}

// ------------------------- weight prep ----------------------------------------
__global__ void prep_w(const float* __restrict__ src, int srcStride, int rows,
                       int rowOffset)
{
    int idx = blockIdx.x * blockDim.x + threadIdx.x;
    if (idx >= rows * KPAD) return;
    int r = idx / KPAD, k = idx - r * KPAD;
    float x = (k < FF) ? src[(size_t)r * srcStride + k] : 0.f;
    __nv_bfloat16 h = __float2bfloat16(x);
    __nv_bfloat16 l = __float2bfloat16(x - __bfloat162float(h));
    g_whi[(size_t)(rowOffset + r) * KPAD + k] = h;
    g_wlo[(size_t)(rowOffset + r) * KPAD + k] = l;
}

__global__ void prep_decb(const float* __restrict__ ab, const float* __restrict__ bb)
{
    int i = threadIdx.x;   // 64
    float v = 0.f;
    if (i < 39) v = ab[i];
    else if (i < 49) v = bb[i - 39];
    g_decb[i] = v;
}

// ------------------------- split-bf16 tensor GEMM -----------------------------
// C[M,Nn] = act(A[M,200] @ W[Nn,200]^T + bias + rowAdd); M % 128 == 0, Nn even.
// W pre-split into g_whi/g_wlo planes at rowOffset, KPAD columns.
// smem layout (bytes): A_hi 0..10240, A_lo 10240.., B_hi 20480.., B_lo 25600..
#define SA_HI 0
#define SA_LO 10240
#define SB_HI 20480
#define SB_LO 25600

template<int ACT>
__global__ __launch_bounds__(256) void tgemm(
    const float* __restrict__ A,
    const __nv_bfloat16* __restrict__ Whi, const __nv_bfloat16* __restrict__ Wlo,
    const float* __restrict__ bias, float* __restrict__ C,
    int M, int Nn, const float* __restrict__ rowAdd, int rpg)
{
    __shared__ __align__(16) char sm[30720];
    const uint32_t sb = smem_u32(sm);
    const int tid = threadIdx.x, lane = tid & 31, wid = tid >> 5;
    const int bm = blockIdx.y * 128, bn = blockIdx.x * 64;
    const int wm = (wid >> 1) * 32, wn = (wid & 1) * 32;

    float acc[2][4][4];
    #pragma unroll
    for (int i = 0; i < 2; i++)
        #pragma unroll
        for (int j = 0; j < 4; j++)
            #pragma unroll
            for (int k = 0; k < 4; k++) acc[i][j][k] = 0.f;

    // staging mappings
    const int ar = tid >> 1, acb = (tid & 1) * 16;        // A: 128 rows x 32 cols fp32
    const float* Arow = A + (size_t)(bm + ar) * FF;
    const int br = tid >> 2, bc = (tid & 3) * 8;          // B: 64 rows x 32 cols bf16
    const int wrow = bn + br;
    const bool wv = (wrow < Nn);
    const __nv_bfloat16* WHrow = Whi + (size_t)(wv ? wrow : 0) * KPAD;
    const __nv_bfloat16* WLrow = Wlo + (size_t)(wv ? wrow : 0) * KPAD;

    for (int t = 0; t < NCH; t++) {
        const int k0 = t * 32;
        // global loads first (overlap with prior compute)
        float4 av[4];
        #pragma unroll
        for (int i = 0; i < 4; i++) {
            int k = k0 + acb + i * 4;
            av[i] = (k < FF) ? *(const float4*)(Arow + k) : make_float4(0.f, 0.f, 0.f, 0.f);
        }
        uint4 bhv = wv ? *(const uint4*)(WHrow + k0 + bc) : make_uint4(0, 0, 0, 0);
        uint4 blv = wv ? *(const uint4*)(WLrow + k0 + bc) : make_uint4(0, 0, 0, 0);

        __syncthreads();
        #pragma unroll
        for (int i = 0; i < 4; i++) {
            int c = acb + i * 4;
            __nv_bfloat162 h0 = __floats2bfloat162_rn(av[i].x, av[i].y);
            __nv_bfloat162 h1 = __floats2bfloat162_rn(av[i].z, av[i].w);
            __nv_bfloat162 l0 = __floats2bfloat162_rn(av[i].x - __bfloat162float(h0.x),
                                                      av[i].y - __bfloat162float(h0.y));
            __nv_bfloat162 l1 = __floats2bfloat162_rn(av[i].z - __bfloat162float(h1.x),
                                                      av[i].w - __bfloat162float(h1.y));
            char* p = sm + SA_HI + ar * 80 + c * 2;
            *(__nv_bfloat162*)p = h0; *(__nv_bfloat162*)(p + 4) = h1;
            char* q = sm + SA_LO + ar * 80 + c * 2;
            *(__nv_bfloat162*)q = l0; *(__nv_bfloat162*)(q + 4) = l1;
        }
        *(uint4*)(sm + SB_HI + br * 80 + bc * 2) = bhv;
        *(uint4*)(sm + SB_LO + br * 80 + bc * 2) = blv;
        __syncthreads();

        #pragma unroll
        for (int ks = 0; ks < 32; ks += 16) {
            uint32_t ah[2][4], alo[2][4], bh[2][4], blo[2][4];
            const int arow = lane & 15;
            const int akc = ks + ((lane >> 4) << 3);
            #pragma unroll
            for (int mi = 0; mi < 2; mi++) {
                uint32_t addr = sb + SA_HI + (uint32_t)(wm + mi * 16 + arow) * 80
                              + (uint32_t)akc * 2;
                ldsm4(ah[mi], addr);
                ldsm4(alo[mi], addr + (SA_LO - SA_HI));
            }
            const int brow = lane & 7, sel = lane >> 3;
            const int nOff = (sel >> 1) * 8, kOff = (sel & 1) * 8;
            #pragma unroll
            for (int p = 0; p < 2; p++) {
                uint32_t addr = sb + SB_HI + (uint32_t)(wn + p * 16 + nOff + brow) * 80
                              + (uint32_t)(ks + kOff) * 2;
                ldsm4(bh[p], addr);
                ldsm4(blo[p], addr + (SB_LO - SB_HI));
            }
            #pragma unroll
            for (int mi = 0; mi < 2; mi++)
                #pragma unroll
                for (int ni = 0; ni < 4; ni++) {
                    const uint32_t* b2h = &bh[ni >> 1][(ni & 1) * 2];
                    const uint32_t* b2l = &blo[ni >> 1][(ni & 1) * 2];
                    mma_bf16(acc[mi][ni], ah[mi], b2h);
                    mma_bf16(acc[mi][ni], ah[mi], b2l);
                    mma_bf16(acc[mi][ni], alo[mi], b2h);
                }
        }
    }

    // epilogue
    const int lr = lane >> 2, lc = (lane & 3) * 2;
    #pragma unroll
    for (int mi = 0; mi < 2; mi++) {
        #pragma unroll
        for (int hh = 0; hh < 2; hh++) {
            int m = bm + wm + mi * 16 + hh * 8 + lr;
            float* crow = C + (size_t)m * Nn;
            const float* ra = rowAdd ? (rowAdd + (size_t)(m / rpg) * Nn) : nullptr;
            #pragma unroll
            for (int ni = 0; ni < 4; ni++) {
                int n = bn + wn + ni * 8 + lc;
                if (n >= Nn) continue;
                float v0 = acc[mi][ni][hh * 2 + 0];
                float v1 = acc[mi][ni][hh * 2 + 1];
                if (bias) { v0 += bias[n]; v1 += bias[n + 1]; }
                if (ra)   { v0 += ra[n];   v1 += ra[n + 1]; }
                if (ACT == 1) { v0 = (v0 > 0.f) ? v0 : expm1f(v0);
                                v1 = (v1 > 0.f) ? v1 : expm1f(v1); }
                else if (ACT == 2) { v0 = fmaxf(v0, 0.f); v1 = fmaxf(v1, 0.f); }
                *(float2*)&crow[n] = make_float2(v0, v1);
            }
        }
    }
}

// ------------------------- mol phase init ------------------------------------
__global__ __launch_bounds__(256) void mol_pre_kernel(
    const float* __restrict__ molf, const float* __restrict__ actf,
    float* __restrict__ h0)
{
    int b = blockIdx.x;
    int tid = threadIdx.x;
    __shared__ float dots[LL];
    __shared__ float red[16];
    const float* mf = molf + (size_t)b * FF;
    int lane = tid & 31, warp = tid >> 5;

    for (int l = warp; l < LL; l += 8) {
        const float* af = actf + ((size_t)b * LL + l) * FF;
        float s = 0.f;
        for (int f = lane; f < FF; f += 32) s += mf[f] * af[f];
        #pragma unroll
        for (int o = 16; o > 0; o >>= 1) s += __shfl_xor_sync(0xffffffffu, s, o);
        if (lane == 0) dots[l] = s;
    }
    __syncthreads();

    float v = dots[tid];
    float m = v;
    #pragma unroll
    for (int o = 16; o > 0; o >>= 1) m = fmaxf(m, __shfl_xor_sync(0xffffffffu, m, o));
    if (lane == 0) red[warp] = m;
    __syncthreads();
    float mx = red[0];
    #pragma unroll
    for (int i = 1; i < 8; i++) mx = fmaxf(mx, red[i]);
    float e = expf(v - mx);
    float s = e;
    #pragma unroll
    for (int o = 16; o > 0; o >>= 1) s += __shfl_xor_sync(0xffffffffu, s, o);
    if (lane == 0) red[8 + warp] = s;
    __syncthreads();
    float tot = 0.f;
    #pragma unroll
    for (int i = 0; i < 8; i++) tot += red[8 + i];
    __syncthreads();
    dots[tid] = e / tot;
    __syncthreads();

    size_t base = (size_t)b * LL * FF;
    for (int i = tid; i < LL * FF; i += 256) {
        int l = i / FF, f = i - l * FF;
        h0[base + i] = dots[l] * mf[f] + actf[base + i];
    }
}

// ------------------------- GRU gate combine ----------------------------------
__global__ __launch_bounds__(256) void gru_combine_kernel(
    const float* __restrict__ gi, const float* __restrict__ gh,
    const float* __restrict__ hin, float* __restrict__ hout,
    float* __restrict__ actout, int total)
{
    int idx = blockIdx.x * blockDim.x + threadIdx.x;
    if (idx >= total) return;
    int m = idx / FF, f = idx - m * FF;
    size_t b3 = (size_t)m * F3;
    float ir = gi[b3 + f], iz = gi[b3 + FF + f], in_ = gi[b3 + 2 * FF + f];
    float hr = gh[b3 + f], hz = gh[b3 + FF + f], hn = gh[b3 + 2 * FF + f];
    float r = 1.f / (1.f + expf(-(ir + hr)));
    float z = 1.f / (1.f + expf(-(iz + hz)));
    float n = tanhf(in_ + r * hn);
    float h = hin[idx];
    float o = (1.f - z) * n + z * h;
    if (hout) hout[idx] = o;
    actout[idx] = fmaxf(o, 0.f);
}

// ------------------------- neighbor attention context ------------------------
__global__ __launch_bounds__(256) void attn_ctx_kernel(
    const float* __restrict__ s1, const float* __restrict__ s2,
    const float* __restrict__ tt, const int* __restrict__ deg,
    float* __restrict__ ctx)
{
    int bl = blockIdx.x;
    int b = bl >> 8;
    int tid = threadIdx.x;
    __shared__ int sidx[NNB];
    if (tid < NNB) sidx[tid] = deg[(size_t)bl * NNB + tid];
    __syncthreads();
    if (tid >= FF) return;
    int f = tid;
    float s1v = s1[(size_t)bl * FF + f];
    float sc[NNB];
    float mx = -3.4e38f;
    #pragma unroll
    for (int n = 0; n < NNB; n++) {
        int j = sidx[n];
        float v = s1v + s2[((size_t)b * LL + j) * FF + f];
        v = (v >= 0.f) ? v : 0.01f * v;
        if (j == LL - 1) v += -9e8f;
        sc[n] = v;
        mx = fmaxf(mx, v);
    }
    float sum = 0.f;
    #pragma unroll
    for (int n = 0; n < NNB; n++) { sc[n] = expf(sc[n] - mx); sum += sc[n]; }
    float inv = 1.f / sum;
    float c = 0.f;
    #pragma unroll
    for (int n = 0; n < NNB; n++) {
        int j = sidx[n];
        if (j != LL - 1)
            c += sc[n] * inv * tt[((size_t)b * LL + j) * FF + f];
    }
    c = (c > 0.f) ? c : expm1f(c);
    ctx[(size_t)bl * FF + f] = c;
}

// ------------------------- decoders ------------------------------------------
__device__ __forceinline__ void seg_softmax_acc(const float* v, float* y, int lo, int hi) {
    float m = -3.4e38f;
    for (int i = lo; i < hi; i++) m = fmaxf(m, v[i]);
    float s = 0.f;
    for (int i = lo; i < hi; i++) s += expf(v[i] - m);
    float inv = 1.f / s;
    for (int i = lo; i < hi; i++) y[i] += expf(v[i] - m) * inv;
}
__device__ __forceinline__ float sigf(float x) { return 1.f / (1.f + expf(-x)); }

__global__ __launch_bounds__(256) void atom_act_kernel(
    const float* __restrict__ dec, float* __restrict__ out, int rows)
{
    int m = blockIdx.x * blockDim.x + threadIdx.x;
    if (m >= rows) return;
    const float* x = dec + (size_t)m * 64;
    float v[39], y[39];
    #pragma unroll
    for (int i = 0; i < 39; i++) { v[i] = x[i]; y[i] = 0.f; }
    seg_softmax_acc(v, y, 0, 16);
    seg_softmax_acc(v, y, 16, 22);
    seg_softmax_acc(v, y, 24, 30);
    seg_softmax_acc(v, y, 31, 36);
    y[24] += fmaxf(v[24], 0.f);
    y[30] += sigf(v[30]);
    y[36] += sigf(v[36]);
    y[37] += sigf(v[37]);
    y[38] += sigf(v[38]);
    float* o = out + (size_t)m * 39;
    #pragma unroll
    for (int i = 0; i < 39; i++) o[i] = y[i];
}

__global__ __launch_bounds__(256) void bond_act_kernel(
    const float* __restrict__ dec, const int* __restrict__ deg,
    float* __restrict__ out, int total)
{
    int id = blockIdx.x * blockDim.x + threadIdx.x;
    if (id >= total) return;                      // total = BL*NNB
    int bl = id / NNB;
    int b = bl >> 8;
    int j = deg[id];
    const float* a = dec + (size_t)bl * 64 + 39;
    const float* c = dec + ((size_t)b * LL + j) * 64 + 49;
    float v[10], y[10];
    #pragma unroll
    for (int k = 0; k < 10; k++) { v[k] = a[k] + c[k]; y[k] = 0.f; }
    seg_softmax_acc(v, y, 0, 4);
    seg_softmax_acc(v, y, 6, 10);
    y[4] += sigf(v[4]);
    y[5] += sigf(v[5]);
    float* o = out + (size_t)id * 10;
    #pragma unroll
    for (int k = 0; k < 10; k++) o[k] = y[k];
}

// ------------------------- host orchestration --------------------------------
static inline dim3 tg_grid(int M, int N) {
    return dim3((N + 63) / 64, M / 128);
}
static inline void prep(const float* src, int stride, int rows, int rowOff) {
    prep_w<<<(rows * KPAD + 255) / 256, 256>>>(src, stride, rows, rowOff);
}

extern "C" void kernel_launch(void* const* d_in, const int* in_sizes, int n_in,
                              void* d_out, int out_size)
{
    const int*   deg        = (const int*)  d_in[2];
    const float* molf       = (const float*)d_in[5];
    const float* actf       = (const float*)d_in[6];
    const float* atom_fc_w  = (const float*)d_in[7];
    const float* atom_fc_b  = (const float*)d_in[8];
    const float* bond_fc_w  = (const float*)d_in[9];
    const float* bond_fc_b  = (const float*)d_in[10];
    const float* align_w    = (const float*)d_in[11];
    const float* align_b    = (const float*)d_in[12];
    const float* attend_w   = (const float*)d_in[13];
    const float* attend_b   = (const float*)d_in[14];
    const float* gru_wih    = (const float*)d_in[15];
    const float* gru_whh    = (const float*)d_in[16];
    const float* gru_bih    = (const float*)d_in[17];
    const float* gru_bhh    = (const float*)d_in[18];
    const float* mol_al_w   = (const float*)d_in[19];
    const float* mol_al_b   = (const float*)d_in[20];
    const float* mgru_wih   = (const float*)d_in[21];
    const float* mgru_whh   = (const float*)d_in[22];
    const float* mgru_bih   = (const float*)d_in[23];
    const float* mgru_bhh   = (const float*)d_in[24];
    float* out = (float*)d_out;

    float *p_h, *p_act, *p_ctx, *p_gi, *p_gh, *p_s1, *p_s2, *p_t, *p_molW, *p_dec, *p_decb;
    __nv_bfloat16 *p_whi, *p_wlo;
    cudaGetSymbolAddress((void**)&p_h,    g_h);
    cudaGetSymbolAddress((void**)&p_act,  g_act);
    cudaGetSymbolAddress((void**)&p_ctx,  g_ctx);
    cudaGetSymbolAddress((void**)&p_gi,   g_gi);
    cudaGetSymbolAddress((void**)&p_gh,   g_gh);
    cudaGetSymbolAddress((void**)&p_s1,   g_s1);
    cudaGetSymbolAddress((void**)&p_s2,   g_s2);
    cudaGetSymbolAddress((void**)&p_t,    g_t);
    cudaGetSymbolAddress((void**)&p_molW, g_molW);
    cudaGetSymbolAddress((void**)&p_dec,  g_dec);
    cudaGetSymbolAddress((void**)&p_decb, g_decb);
    cudaGetSymbolAddress((void**)&p_whi,  g_whi);
    cudaGetSymbolAddress((void**)&p_wlo,  g_wlo);

    // ---- weight prep (split bf16) ----
    prep(mol_al_w,        2 * FF, FF, W_MOL0);
    prep(mol_al_w + FF,   2 * FF, FF, W_MOL1);
    prep(mgru_wih,        FF, F3, W_MGI);
    prep(mgru_whh,        FF, F3, W_MGH);
    for (int d = 0; d < RROUNDS; d++) {
        const float* aw = align_w + (size_t)d * FF * 2 * FF;
        prep(aw,                               2 * FF, FF, W_RND(d) + 0);
        prep(aw + FF,                          2 * FF, FF, W_RND(d) + 200);
        prep(attend_w + (size_t)d * FF * FF,   FF,     FF, W_RND(d) + 400);
        prep(gru_wih + (size_t)d * F3 * FF,    FF,     F3, W_RND(d) + 600);
        prep(gru_whh + (size_t)d * F3 * FF,    FF,     F3, W_RND(d) + 1200);
    }
    prep(atom_fc_w,       FF,     39, W_DEC);
    prep(bond_fc_w,       2 * FF, 10, W_DEC + 39);
    prep(bond_fc_w + FF,  2 * FF, 10, W_DEC + 49);
    prep_decb<<<1, 64>>>(atom_fc_b, bond_fc_b);

    const __nv_bfloat16* WH = p_whi;
    const __nv_bfloat16* WL = p_wlo;

    // 1) mol phase init
    mol_pre_kernel<<<BB, 256>>>(molf, actf, p_h);

    // 2) molW = molf @ Wm0^T + b
    tgemm<0><<<tg_grid(BB, FF), 256>>>(molf, WH + (size_t)W_MOL0 * KPAD, WL + (size_t)W_MOL0 * KPAD,
                                       mol_al_b, p_molW, BB, FF, nullptr, 1);

    // 3) T GRU steps
    for (int t = 0; t < TSTEPS; t++) {
        tgemm<1><<<tg_grid(BL, FF), 256>>>(p_h, WH + (size_t)W_MOL1 * KPAD, WL + (size_t)W_MOL1 * KPAD,
                                           nullptr, p_ctx, BL, FF, p_molW, LL);
        tgemm<0><<<tg_grid(BL, F3), 256>>>(p_ctx, WH + (size_t)W_MGI * KPAD, WL + (size_t)W_MGI * KPAD,
                                           mgru_bih, p_gi, BL, F3, nullptr, 1);
        tgemm<0><<<tg_grid(BL, F3), 256>>>(p_h, WH + (size_t)W_MGH * KPAD, WL + (size_t)W_MGH * KPAD,
                                           mgru_bhh, p_gh, BL, F3, nullptr, 1);
        gru_combine_kernel<<<(BL * FF + 255) / 256, 256>>>(p_gi, p_gh, p_h, p_h, p_act, BL * FF);
    }

    // 4) rounds
    for (int d = 0; d < RROUNDS; d++) {
        size_t rb = (size_t)W_RND(d) * KPAD;
        tgemm<0><<<tg_grid(BL, FF), 256>>>(p_act, WH + rb, WL + rb,
                                           align_b + (size_t)d * FF, p_s1, BL, FF, nullptr, 1);
        tgemm<0><<<tg_grid(BL, FF), 256>>>(p_act, WH + rb + 200 * KPAD, WL + rb + 200 * KPAD,
                                           nullptr, p_s2, BL, FF, nullptr, 1);
        tgemm<0><<<tg_grid(BL, FF), 256>>>(p_act, WH + rb + 400 * KPAD, WL + rb + 400 * KPAD,
                                           attend_b + (size_t)d * FF, p_t, BL, FF, nullptr, 1);
        attn_ctx_kernel<<<BL, 256>>>(p_s1, p_s2, p_t, deg, p_ctx);
        tgemm<0><<<tg_grid(BL, F3), 256>>>(p_ctx, WH + rb + 600 * KPAD, WL + rb + 600 * KPAD,
                                           gru_bih + (size_t)d * F3, p_gi, BL, F3, nullptr, 1);
        tgemm<0><<<tg_grid(BL, F3), 256>>>(p_act, WH + rb + 1200 * KPAD, WL + rb + 1200 * KPAD,
                                           gru_bhh + (size_t)d * F3, p_gh, BL, F3, nullptr, 1);
        gru_combine_kernel<<<(BL * FF + 255) / 256, 256>>>(p_gi, p_gh, p_act, nullptr, p_act, BL * FF);
    }

    // 5) decode (atom + bond fused into one N=64 GEMM)
    tgemm<0><<<tg_grid(BL, 64), 256>>>(p_act, WH + (size_t)W_DEC * KPAD, WL + (size_t)W_DEC * KPAD,
                                       p_decb, p_dec, BL, 64, nullptr, 1);

    atom_act_kernel<<<(BL + 255) / 256, 256>>>(p_dec, out, BL);
    bond_act_kernel<<<(BL * NNB + 255) / 256, 256>>>(p_dec, deg,
                                                     out + (size_t)BL * 39, BL * NNB);
}

// round 7
// speedup vs baseline: 2.2154x; 1.7243x over previous
#include <cuda_runtime.h>
#include <cuda_bf16.h>
#include <math.h>
#include <stdint.h>

// Problem constants
#define BB 128
#define LL 256
#define NNB 8
#define FF 200
#define F3 600
#define BL (BB*LL)           // 32768
#define RROUNDS 2
#define TSTEPS 2
#define KPAD 224
#define NCH 7                // 224/32 k-chunks

// ------------------------- scratch (device globals) -------------------------
__device__ float g_h[BL*FF];
__device__ float g_act[BL*FF];
__device__ float g_molW[BB*FF];
__device__ float g_sst[BL*F3];
__device__ float g_gi[BL*F3];
__device__ float g_gh[BL*F3];
__device__ float g_dec[BL*64];
__device__ float g_decb[64];
__device__ float g_rb[RROUNDS*F3];

// split-bf16 activation planes (KPAD stride, pads stay zero from static init)
__device__ __align__(16) __nv_bfloat16 g_h_hi[BL*KPAD];
__device__ __align__(16) __nv_bfloat16 g_h_lo[BL*KPAD];
__device__ __align__(16) __nv_bfloat16 g_a_hi[BL*KPAD];
__device__ __align__(16) __nv_bfloat16 g_a_lo[BL*KPAD];
__device__ __align__(16) __nv_bfloat16 g_c_hi[BL*KPAD];
__device__ __align__(16) __nv_bfloat16 g_c_lo[BL*KPAD];
__device__ __align__(16) __nv_bfloat16 g_mf_hi[BB*KPAD];
__device__ __align__(16) __nv_bfloat16 g_mf_lo[BB*KPAD];

// packed split-bf16 weight planes [row][KPAD]
#define WROWS 5264
__device__ __align__(16) __nv_bfloat16 g_whi[WROWS*KPAD];
__device__ __align__(16) __nv_bfloat16 g_wlo[WROWS*KPAD];

// weight row offsets
#define W_MOL0 0
#define W_MOL1 200
#define W_MGI  400
#define W_MGH  1000
#define W_RND(d) (1600 + (d)*1800)   // +0 s1|s2|t (600 rows), +600 gwi, +1200 gwh
#define W_DEC  5200

// ------------------------- helpers -------------------------------------------
__device__ __forceinline__ uint32_t smem_u32(const void* p) {
    uint32_t a;
    asm("{ .reg .u64 t; cvta.to.shared.u64 t, %1; cvt.u32.u64 %0, t; }"
        : "=r"(a) : "l"(p));
    return a;
}
__device__ __forceinline__ void ldsm4(uint32_t* r, uint32_t a) {
    asm volatile("ldmatrix.sync.aligned.m8n8.x4.shared.b16 {%0,%1,%2,%3}, [%4];"
        : "=r"(r[0]), "=r"(r[1]), "=r"(r[2]), "=r"(r[3]) : "r"(a));
}
__device__ __forceinline__ void mma_bf16(float* c, const uint32_t* a, const uint32_t* b) {
    asm volatile("mma.sync.aligned.m16n8k16.row.col.f32.bf16.bf16.f32 "
        "{%0,%1,%2,%3}, {%4,%5,%6,%7}, {%8,%9}, {%0,%1,%2,%3};"
        : "+f"(c[0]), "+f"(c[1]), "+f"(c[2]), "+f"(c[3])
        : "r"(a[0]), "r"(a[1]), "r"(a[2]), "r"(a[3]), "r"(b[0]), "r"(b[1]));
}
__device__ __forceinline__ void cpa16(uint32_t dst, const void* src, int srcSize) {
    asm volatile("cp.async.cg.shared.global [%0], [%1], 16, %2;"
        :: "r"(dst), "l"(src), "r"(srcSize));
}
__device__ __forceinline__ void cp_commit() {
    asm volatile("cp.async.commit_group;" ::: "memory");
}
__device__ __forceinline__ void cp_wait0() {
    asm volatile("cp.async.wait_group 0;" ::: "memory");
}
__device__ __forceinline__ void split2(float v, __nv_bfloat16* hi, __nv_bfloat16* lo) {
    __nv_bfloat16 h = __float2bfloat16(v);
    *hi = h;
    *lo = __float2bfloat16(v - __bfloat162float(h));
}

// ------------------------- weight / input prep --------------------------------
__global__ void prep_w(const float* __restrict__ src, int srcStride, int rows,
                       int rowOffset)
{
    int idx = blockIdx.x * blockDim.x + threadIdx.x;
    if (idx >= rows * KPAD) return;
    int r = idx / KPAD, k = idx - r * KPAD;
    float x = (k < FF) ? src[(size_t)r * srcStride + k] : 0.f;
    split2(x, &g_whi[(size_t)(rowOffset + r) * KPAD + k],
              &g_wlo[(size_t)(rowOffset + r) * KPAD + k]);
}

__global__ void split_molf(const float* __restrict__ src)
{
    int idx = blockIdx.x * blockDim.x + threadIdx.x;
    if (idx >= BB * KPAD) return;
    int r = idx / KPAD, k = idx - r * KPAD;
    float x = (k < FF) ? src[(size_t)r * FF + k] : 0.f;
    split2(x, &g_mf_hi[idx], &g_mf_lo[idx]);
}

__global__ void prep_decb(const float* __restrict__ ab, const float* __restrict__ bb)
{
    int i = threadIdx.x;   // 64
    float v = 0.f;
    if (i < 39) v = ab[i];
    else if (i < 49) v = bb[i - 39];
    g_decb[i] = v;
}

__global__ void prep_rb(const float* __restrict__ align_b, const float* __restrict__ attend_b)
{
    int d = blockIdx.x, i = threadIdx.x;   // 600
    float v = 0.f;
    if (i < 200) v = align_b[d * FF + i];
    else if (i >= 400) v = attend_b[d * FF + i - 400];
    g_rb[d * F3 + i] = v;
}

// ------------------------- split-bf16 tensor GEMM -----------------------------
// C = act(A @ W^T + bias + rowAdd); A pre-split (hi/lo, KPAD stride), M%128==0.
// OUT: 0 -> fp32 C;  1 -> split-bf16 planes Chi/Clo (KPAD stride).
#define PITCH 80
#define REG 10240            // 128 * PITCH
#define STG 40960            // 4 regions per stage
#define TG_SMEM (2*STG)      // 81920

template<int ACT, int OUT>
__global__ __launch_bounds__(256) void tgemm(
    const __nv_bfloat16* __restrict__ Ahi, const __nv_bfloat16* __restrict__ Alo,
    const __nv_bfloat16* __restrict__ Whi, const __nv_bfloat16* __restrict__ Wlo,
    const float* __restrict__ bias, float* __restrict__ C,
    __nv_bfloat16* __restrict__ Chi, __nv_bfloat16* __restrict__ Clo,
    int M, int Nn, const float* __restrict__ rowAdd, int rpg)
{
    extern __shared__ __align__(16) char sm[];
    const uint32_t sb = smem_u32(sm);
    const int tid = threadIdx.x, lane = tid & 31, wid = tid >> 5;
    const int bm = blockIdx.y * 128, bn = blockIdx.x * 128;
    const int wm = (wid & 3) * 32, wn = (wid >> 2) * 64;

    float acc[2][8][4];
    #pragma unroll
    for (int i = 0; i < 2; i++)
        #pragma unroll
        for (int j = 0; j < 8; j++)
            #pragma unroll
            for (int k = 0; k < 4; k++) acc[i][j][k] = 0.f;

    // loader mapping: 2 chunks/region/thread
    const int c0 = tid, c1 = tid + 256;
    const int r0 = c0 >> 2, q0 = (c0 & 3) * 16;
    const int r1 = c1 >> 2, q1 = (c1 & 3) * 16;
    const int n0 = bn + r0, n1 = bn + r1;
    const int v0 = (n0 < Nn) ? 16 : 0, v1 = (n1 < Nn) ? 16 : 0;
    const char* pAh0 = (const char*)(Ahi + (size_t)(bm + r0) * KPAD) + q0;
    const char* pAh1 = (const char*)(Ahi + (size_t)(bm + r1) * KPAD) + q1;
    const char* pAl0 = (const char*)(Alo + (size_t)(bm + r0) * KPAD) + q0;
    const char* pAl1 = (const char*)(Alo + (size_t)(bm + r1) * KPAD) + q1;
    const char* pBh0 = (const char*)(Whi + (size_t)(v0 ? n0 : 0) * KPAD) + q0;
    const char* pBh1 = (const char*)(Whi + (size_t)(v1 ? n1 : 0) * KPAD) + q1;
    const char* pBl0 = (const char*)(Wlo + (size_t)(v0 ? n0 : 0) * KPAD) + q0;
    const char* pBl1 = (const char*)(Wlo + (size_t)(v1 ? n1 : 0) * KPAD) + q1;
    const uint32_t d0 = (uint32_t)(r0 * PITCH) + q0;
    const uint32_t d1 = (uint32_t)(r1 * PITCH) + q1;

    auto stage_load = [&](int t, int st) {
        const int kb = t * 64;   // bytes into K
        const uint32_t s = sb + st * STG;
        cpa16(s + d0,           pAh0 + kb, 16);
        cpa16(s + d1,           pAh1 + kb, 16);
        cpa16(s + REG + d0,     pAl0 + kb, 16);
        cpa16(s + REG + d1,     pAl1 + kb, 16);
        cpa16(s + 2*REG + d0,   pBh0 + kb, v0);
        cpa16(s + 2*REG + d1,   pBh1 + kb, v1);
        cpa16(s + 3*REG + d0,   pBl0 + kb, v0);
        cpa16(s + 3*REG + d1,   pBl1 + kb, v1);
    };

    stage_load(0, 0);
    cp_commit();

    const int arow = lane & 15;
    const int brow = lane & 7, sel = lane >> 3;
    const int nOff = (sel >> 1) * 8, kOff = (sel & 1) * 8;

    for (int t = 0; t < NCH; t++) {
        cp_wait0();
        __syncthreads();
        if (t + 1 < NCH) { stage_load(t + 1, (t + 1) & 1); cp_commit(); }
        const uint32_t s = sb + (t & 1) * STG;

        #pragma unroll
        for (int ks = 0; ks < 32; ks += 16) {
            uint32_t ah[2][4], al[2][4];
            const uint32_t akc = (uint32_t)(ks + ((lane >> 4) << 3)) * 2;
            #pragma unroll
            for (int mi = 0; mi < 2; mi++) {
                uint32_t ad = s + (uint32_t)(wm + mi * 16 + arow) * PITCH + akc;
                ldsm4(ah[mi], ad);
                ldsm4(al[mi], ad + REG);
            }
            #pragma unroll
            for (int half = 0; half < 2; half++) {
                uint32_t bh[2][4], blo[2][4];
                #pragma unroll
                for (int p = 0; p < 2; p++) {
                    uint32_t bd = s + 2*REG
                        + (uint32_t)(wn + (half * 2 + p) * 16 + nOff + brow) * PITCH
                        + (uint32_t)(ks + kOff) * 2;
                    ldsm4(bh[p], bd);
                    ldsm4(blo[p], bd + REG);
                }
                #pragma unroll
                for (int mi = 0; mi < 2; mi++)
                    #pragma unroll
                    for (int nj = 0; nj < 4; nj++) {
                        const uint32_t* b2h = &bh[nj >> 1][(nj & 1) * 2];
                        const uint32_t* b2l = &blo[nj >> 1][(nj & 1) * 2];
                        float* a = acc[mi][half * 4 + nj];
                        mma_bf16(a, ah[mi], b2h);
                        mma_bf16(a, ah[mi], b2l);
                        mma_bf16(a, al[mi], b2h);
                    }
            }
        }
        __syncthreads();
    }

    // epilogue
    const int lr = lane >> 2, lc = (lane & 3) * 2;
    #pragma unroll
    for (int mi = 0; mi < 2; mi++) {
        #pragma unroll
        for (int hh = 0; hh < 2; hh++) {
            int m = bm + wm + mi * 16 + hh * 8 + lr;
            const float* ra = rowAdd ? (rowAdd + (size_t)(m / rpg) * Nn) : nullptr;
            #pragma unroll
            for (int ni = 0; ni < 8; ni++) {
                int n = bn + wn + ni * 8 + lc;
                if (n >= Nn) continue;
                float v0f = acc[mi][ni][hh * 2 + 0];
                float v1f = acc[mi][ni][hh * 2 + 1];
                if (bias) { v0f += bias[n]; v1f += bias[n + 1]; }
                if (ra)   { v0f += ra[n];   v1f += ra[n + 1]; }
                if (ACT == 1) { v0f = (v0f > 0.f) ? v0f : expm1f(v0f);
                                v1f = (v1f > 0.f) ? v1f : expm1f(v1f); }
                else if (ACT == 2) { v0f = fmaxf(v0f, 0.f); v1f = fmaxf(v1f, 0.f); }
                if (OUT == 0) {
                    *(float2*)&C[(size_t)m * Nn + n] = make_float2(v0f, v1f);
                } else {
                    __nv_bfloat162 h2 = __floats2bfloat162_rn(v0f, v1f);
                    __nv_bfloat162 l2 = __floats2bfloat162_rn(
                        v0f - __bfloat162float(h2.x), v1f - __bfloat162float(h2.y));
                    *(__nv_bfloat162*)&Chi[(size_t)m * KPAD + n] = h2;
                    *(__nv_bfloat162*)&Clo[(size_t)m * KPAD + n] = l2;
                }
            }
        }
    }
}

// ------------------------- mol phase init ------------------------------------
__global__ __launch_bounds__(256) void mol_pre_kernel(
    const float* __restrict__ molf, const float* __restrict__ actf)
{
    int b = blockIdx.x;
    int tid = threadIdx.x;
    __shared__ float dots[LL];
    __shared__ float red[16];
    const float* mf = molf + (size_t)b * FF;
    int lane = tid & 31, warp = tid >> 5;

    for (int l = warp; l < LL; l += 8) {
        const float* af = actf + ((size_t)b * LL + l) * FF;
        float s = 0.f;
        for (int f = lane; f < FF; f += 32) s += mf[f] * af[f];
        #pragma unroll
        for (int o = 16; o > 0; o >>= 1) s += __shfl_xor_sync(0xffffffffu, s, o);
        if (lane == 0) dots[l] = s;
    }
    __syncthreads();

    float v = dots[tid];
    float m = v;
    #pragma unroll
    for (int o = 16; o > 0; o >>= 1) m = fmaxf(m, __shfl_xor_sync(0xffffffffu, m, o));
    if (lane == 0) red[warp] = m;
    __syncthreads();
    float mx = red[0];
    #pragma unroll
    for (int i = 1; i < 8; i++) mx = fmaxf(mx, red[i]);
    float e = expf(v - mx);
    float s = e;
    #pragma unroll
    for (int o = 16; o > 0; o >>= 1) s += __shfl_xor_sync(0xffffffffu, s, o);
    if (lane == 0) red[8 + warp] = s;
    __syncthreads();
    float tot = 0.f;
    #pragma unroll
    for (int i = 0; i < 8; i++) tot += red[8 + i];
    __syncthreads();
    dots[tid] = e / tot;
    __syncthreads();

    size_t base = (size_t)b * LL * FF;
    for (int i = tid; i < LL * FF; i += 256) {
        int l = i / FF, f = i - l * FF;
        float v2 = dots[l] * mf[f] + actf[base + i];
        g_h[base + i] = v2;
        size_t si = ((size_t)b * LL + l) * KPAD + f;
        split2(v2, &g_h_hi[si], &g_h_lo[si]);
    }
}

// ------------------------- GRU gate combine ----------------------------------
// writes: optional h (fp32 + split), always act (fp32 + split)
__global__ __launch_bounds__(256) void gru_combine_kernel(
    const float* __restrict__ gi, const float* __restrict__ gh,
    const float* __restrict__ hin, int writeH, int total)
{
    int idx = blockIdx.x * blockDim.x + threadIdx.x;
    if (idx >= total) return;
    int m = idx / FF, f = idx - m * FF;
    size_t b3 = (size_t)m * F3;
    float ir = gi[b3 + f], iz = gi[b3 + FF + f], in_ = gi[b3 + 2 * FF + f];
    float hr = gh[b3 + f], hz = gh[b3 + FF + f], hn = gh[b3 + 2 * FF + f];
    float r = 1.f / (1.f + expf(-(ir + hr)));
    float z = 1.f / (1.f + expf(-(iz + hz)));
    float n = tanhf(in_ + r * hn);
    float h = hin[idx];
    float o = (1.f - z) * n + z * h;
    size_t si = (size_t)m * KPAD + f;
    if (writeH) {
        g_h[idx] = o;
        split2(o, &g_h_hi[si], &g_h_lo[si]);
    }
    float a = fmaxf(o, 0.f);
    g_act[idx] = a;
    split2(a, &g_a_hi[si], &g_a_lo[si]);
}

// ------------------------- neighbor attention context ------------------------
__global__ __launch_bounds__(256) void attn_ctx_kernel(
    const float* __restrict__ sst, const int* __restrict__ deg)
{
    int bl = blockIdx.x;
    int b = bl >> 8;
    int tid = threadIdx.x;
    __shared__ int sidx[NNB];
    if (tid < NNB) sidx[tid] = deg[(size_t)bl * NNB + tid];
    __syncthreads();
    if (tid >= FF) return;
    int f = tid;
    float s1v = sst[(size_t)bl * F3 + f];
    float sc[NNB];
    float mx = -3.4e38f;
    #pragma unroll
    for (int n = 0; n < NNB; n++) {
        int j = sidx[n];
        float v = s1v + sst[((size_t)b * LL + j) * F3 + 200 + f];
        v = (v >= 0.f) ? v : 0.01f * v;
        if (j == LL - 1) v += -9e8f;
        sc[n] = v;
        mx = fmaxf(mx, v);
    }
    float sum = 0.f;
    #pragma unroll
    for (int n = 0; n < NNB; n++) { sc[n] = expf(sc[n] - mx); sum += sc[n]; }
    float inv = 1.f / sum;
    float c = 0.f;
    #pragma unroll
    for (int n = 0; n < NNB; n++) {
        int j = sidx[n];
        if (j != LL - 1)
            c += sc[n] * inv * sst[((size_t)b * LL + j) * F3 + 400 + f];
    }
    c = (c > 0.f) ? c : expm1f(c);
    size_t si = (size_t)bl * KPAD + f;
    split2(c, &g_c_hi[si], &g_c_lo[si]);
}

// ------------------------- decoders ------------------------------------------
__device__ __forceinline__ void seg_softmax_acc(const float* v, float* y, int lo, int hi) {
    float m = -3.4e38f;
    for (int i = lo; i < hi; i++) m = fmaxf(m, v[i]);
    float s = 0.f;
    for (int i = lo; i < hi; i++) s += expf(v[i] - m);
    float inv = 1.f / s;
    for (int i = lo; i < hi; i++) y[i] += expf(v[i] - m) * inv;
}
__device__ __forceinline__ float sigf(float x) { return 1.f / (1.f + expf(-x)); }

__global__ __launch_bounds__(256) void atom_act_kernel(
    const float* __restrict__ dec, float* __restrict__ out, int rows)
{
    int m = blockIdx.x * blockDim.x + threadIdx.x;
    if (m >= rows) return;
    const float* x = dec + (size_t)m * 64;
    float v[39], y[39];
    #pragma unroll
    for (int i = 0; i < 39; i++) { v[i] = x[i]; y[i] = 0.f; }
    seg_softmax_acc(v, y, 0, 16);
    seg_softmax_acc(v, y, 16, 22);
    seg_softmax_acc(v, y, 24, 30);
    seg_softmax_acc(v, y, 31, 36);
    y[24] += fmaxf(v[24], 0.f);
    y[30] += sigf(v[30]);
    y[36] += sigf(v[36]);
    y[37] += sigf(v[37]);
    y[38] += sigf(v[38]);
    float* o = out + (size_t)m * 39;
    #pragma unroll
    for (int i = 0; i < 39; i++) o[i] = y[i];
}

__global__ __launch_bounds__(256) void bond_act_kernel(
    const float* __restrict__ dec, const int* __restrict__ deg,
    float* __restrict__ out, int total)
{
    int id = blockIdx.x * blockDim.x + threadIdx.x;
    if (id >= total) return;                      // total = BL*NNB
    int bl = id / NNB;
    int b = bl >> 8;
    int j = deg[id];
    const float* a = dec + (size_t)bl * 64 + 39;
    const float* c = dec + ((size_t)b * LL + j) * 64 + 49;
    float v[10], y[10];
    #pragma unroll
    for (int k = 0; k < 10; k++) { v[k] = a[k] + c[k]; y[k] = 0.f; }
    seg_softmax_acc(v, y, 0, 4);
    seg_softmax_acc(v, y, 6, 10);
    y[4] += sigf(v[4]);
    y[5] += sigf(v[5]);
    float* o = out + (size_t)id * 10;
    #pragma unroll
    for (int k = 0; k < 10; k++) o[k] = y[k];
}

// ------------------------- host orchestration --------------------------------
static inline dim3 tg_grid(int M, int N) {
    return dim3((N + 127) / 128, M / 128);
}
static inline void prep(const float* src, int stride, int rows, int rowOff) {
    prep_w<<<(rows * KPAD + 255) / 256, 256>>>(src, stride, rows, rowOff);
}

extern "C" void kernel_launch(void* const* d_in, const int* in_sizes, int n_in,
                              void* d_out, int out_size)
{
    const int*   deg        = (const int*)  d_in[2];
    const float* molf       = (const float*)d_in[5];
    const float* actf       = (const float*)d_in[6];
    const float* atom_fc_w  = (const float*)d_in[7];
    const float* atom_fc_b  = (const float*)d_in[8];
    const float* bond_fc_w  = (const float*)d_in[9];
    const float* bond_fc_b  = (const float*)d_in[10];
    const float* align_w    = (const float*)d_in[11];
    const float* align_b    = (const float*)d_in[12];
    const float* attend_w   = (const float*)d_in[13];
    const float* attend_b   = (const float*)d_in[14];
    const float* gru_wih    = (const float*)d_in[15];
    const float* gru_whh    = (const float*)d_in[16];
    const float* gru_bih    = (const float*)d_in[17];
    const float* gru_bhh    = (const float*)d_in[18];
    const float* mol_al_w   = (const float*)d_in[19];
    const float* mol_al_b   = (const float*)d_in[20];
    const float* mgru_wih   = (const float*)d_in[21];
    const float* mgru_whh   = (const float*)d_in[22];
    const float* mgru_bih   = (const float*)d_in[23];
    const float* mgru_bhh   = (const float*)d_in[24];
    float* out = (float*)d_out;

    float *p_h, *p_act, *p_molW, *p_sst, *p_gi, *p_gh, *p_dec, *p_decb, *p_rb;
    __nv_bfloat16 *p_whi, *p_wlo, *p_hhi, *p_hlo, *p_ahi, *p_alo, *p_chi, *p_clo, *p_mfhi, *p_mflo;
    cudaGetSymbolAddress((void**)&p_h,    g_h);
    cudaGetSymbolAddress((void**)&p_act,  g_act);
    cudaGetSymbolAddress((void**)&p_molW, g_molW);
    cudaGetSymbolAddress((void**)&p_sst,  g_sst);
    cudaGetSymbolAddress((void**)&p_gi,   g_gi);
    cudaGetSymbolAddress((void**)&p_gh,   g_gh);
    cudaGetSymbolAddress((void**)&p_dec,  g_dec);
    cudaGetSymbolAddress((void**)&p_decb, g_decb);
    cudaGetSymbolAddress((void**)&p_rb,   g_rb);
    cudaGetSymbolAddress((void**)&p_whi,  g_whi);
    cudaGetSymbolAddress((void**)&p_wlo,  g_wlo);
    cudaGetSymbolAddress((void**)&p_hhi,  g_h_hi);
    cudaGetSymbolAddress((void**)&p_hlo,  g_h_lo);
    cudaGetSymbolAddress((void**)&p_ahi,  g_a_hi);
    cudaGetSymbolAddress((void**)&p_alo,  g_a_lo);
    cudaGetSymbolAddress((void**)&p_chi,  g_c_hi);
    cudaGetSymbolAddress((void**)&p_clo,  g_c_lo);
    cudaGetSymbolAddress((void**)&p_mfhi, g_mf_hi);
    cudaGetSymbolAddress((void**)&p_mflo, g_mf_lo);

    cudaFuncSetAttribute(tgemm<0,0>, cudaFuncAttributeMaxDynamicSharedMemorySize, TG_SMEM);
    cudaFuncSetAttribute(tgemm<1,1>, cudaFuncAttributeMaxDynamicSharedMemorySize, TG_SMEM);

    // ---- prep ----
    prep(mol_al_w,        2 * FF, FF, W_MOL0);
    prep(mol_al_w + FF,   2 * FF, FF, W_MOL1);
    prep(mgru_wih,        FF, F3, W_MGI);
    prep(mgru_whh,        FF, F3, W_MGH);
    for (int d = 0; d < RROUNDS; d++) {
        const float* aw = align_w + (size_t)d * FF * 2 * FF;
        prep(aw,                               2 * FF, FF, W_RND(d) + 0);
        prep(aw + FF,                          2 * FF, FF, W_RND(d) + 200);
        prep(attend_w + (size_t)d * FF * FF,   FF,     FF, W_RND(d) + 400);
        prep(gru_wih + (size_t)d * F3 * FF,    FF,     F3, W_RND(d) + 600);
        prep(gru_whh + (size_t)d * F3 * FF,    FF,     F3, W_RND(d) + 1200);
    }
    prep(atom_fc_w,       FF,     39, W_DEC);
    prep(bond_fc_w,       2 * FF, 10, W_DEC + 39);
    prep(bond_fc_w + FF,  2 * FF, 10, W_DEC + 49);
    prep_decb<<<1, 64>>>(atom_fc_b, bond_fc_b);
    prep_rb<<<RROUNDS, F3>>>(align_b, attend_b);
    split_molf<<<(BB * KPAD + 255) / 256, 256>>>(molf);

    const __nv_bfloat16* WH = p_whi;
    const __nv_bfloat16* WL = p_wlo;
    #define WOFF(o) (WH + (size_t)(o) * KPAD), (WL + (size_t)(o) * KPAD)

    // 1) mol phase init (h + split)
    mol_pre_kernel<<<BB, 256>>>(molf, actf);

    // 2) molW = molf @ Wm0^T + b
    tgemm<0,0><<<tg_grid(BB, FF), 256, TG_SMEM>>>(
        p_mfhi, p_mflo, WOFF(W_MOL0), mol_al_b, p_molW, nullptr, nullptr,
        BB, FF, nullptr, 1);

    // 3) T GRU steps
    for (int t = 0; t < TSTEPS; t++) {
        tgemm<1,1><<<tg_grid(BL, FF), 256, TG_SMEM>>>(
            p_hhi, p_hlo, WOFF(W_MOL1), nullptr, nullptr, p_chi, p_clo,
            BL, FF, p_molW, LL);
        tgemm<0,0><<<tg_grid(BL, F3), 256, TG_SMEM>>>(
            p_chi, p_clo, WOFF(W_MGI), mgru_bih, p_gi, nullptr, nullptr,
            BL, F3, nullptr, 1);
        tgemm<0,0><<<tg_grid(BL, F3), 256, TG_SMEM>>>(
            p_hhi, p_hlo, WOFF(W_MGH), mgru_bhh, p_gh, nullptr, nullptr,
            BL, F3, nullptr, 1);
        gru_combine_kernel<<<(BL * FF + 255) / 256, 256>>>(p_gi, p_gh, p_h, 1, BL * FF);
    }

    // 4) rounds
    for (int d = 0; d < RROUNDS; d++) {
        tgemm<0,0><<<tg_grid(BL, F3), 256, TG_SMEM>>>(
            p_ahi, p_alo, WOFF(W_RND(d)), p_rb + (size_t)d * F3, p_sst, nullptr, nullptr,
            BL, F3, nullptr, 1);
        attn_ctx_kernel<<<BL, 256>>>(p_sst, deg);
        tgemm<0,0><<<tg_grid(BL, F3), 256, TG_SMEM>>>(
            p_chi, p_clo, WOFF(W_RND(d) + 600), gru_bih + (size_t)d * F3, p_gi, nullptr, nullptr,
            BL, F3, nullptr, 1);
        tgemm<0,0><<<tg_grid(BL, F3), 256, TG_SMEM>>>(
            p_ahi, p_alo, WOFF(W_RND(d) + 1200), gru_bhh + (size_t)d * F3, p_gh, nullptr, nullptr,
            BL, F3, nullptr, 1);
        gru_combine_kernel<<<(BL * FF + 255) / 256, 256>>>(p_gi, p_gh, p_act, 0, BL * FF);
    }

    // 5) decode (atom + bond fused, N=64)
    tgemm<0,0><<<tg_grid(BL, 64), 256, TG_SMEM>>>(
        p_ahi, p_alo, WOFF(W_DEC), p_decb, p_dec, nullptr, nullptr,
        BL, 64, nullptr, 1);

    atom_act_kernel<<<(BL + 255) / 256, 256>>>(p_dec, out, BL);
    bond_act_kernel<<<(BL * NNB + 255) / 256, 256>>>(p_dec, deg,
                                                     out + (size_t)BL * 39, BL * NNB);
}

// round 8
// speedup vs baseline: 2.3318x; 1.0525x over previous
#include <cuda_runtime.h>
#include <cuda_bf16.h>
#include <math.h>
#include <stdint.h>

#define BB 128
#define LL 256
#define NNB 8
#define FF 200
#define F3 600
#define BL (BB*LL)
#define RROUNDS 2
#define TSTEPS 2
#define KPAD 224
#define NCH 7

__device__ float g_molW[BB*FF];
__device__ float g_sst[BL*F3];
__device__ float g_gi[BL*F3];
__device__ float g_gh[BL*F3];
__device__ float g_dec[BL*64];
__device__ float g_decb[64];
__device__ float g_rb[RROUNDS*F3];

#define APLANE ((size_t)BL*KPAD)
#define MPLANE ((size_t)BB*KPAD)
__device__ __align__(16) __nv_bfloat16 g_hsp[2*BL*KPAD];
__device__ __align__(16) __nv_bfloat16 g_asp[2*BL*KPAD];
__device__ __align__(16) __nv_bfloat16 g_csp[2*BL*KPAD];
__device__ __align__(16) __nv_bfloat16 g_mfsp[2*BB*KPAD];

#define WROWS 5264
#define WPLANE ((size_t)WROWS*KPAD)
__device__ __align__(16) __nv_bfloat16 g_wsp[2*WROWS*KPAD];

#define W_MOL0 0
#define W_MOL1 200
#define W_MGI  400
#define W_MGH  1000
#define W_RND(d) (1600 + (d)*1800)
#define W_DEC  5200
#define NSEG 14

__device__ __forceinline__ uint32_t smem_u32(const void* p) {
    uint32_t a;
    asm("{ .reg .u64 t; cvta.to.shared.u64 t, %1; cvt.u32.u64 %0, t; }"
        : "=r"(a) : "l"(p));
    return a;
}
__device__ __forceinline__ void ldsm4(uint32_t* r, uint32_t a) {
    asm volatile("ldmatrix.sync.aligned.m8n8.x4.shared.b16 {%0,%1,%2,%3}, [%4];"
        : "=r"(r[0]), "=r"(r[1]), "=r"(r[2]), "=r"(r[3]) : "r"(a));
}
__device__ __forceinline__ void mma_bf16(float* c, const uint32_t* a, const uint32_t* b) {
    asm volatile("mma.sync.aligned.m16n8k16.row.col.f32.bf16.bf16.f32 "
        "{%0,%1,%2,%3}, {%4,%5,%6,%7}, {%8,%9}, {%0,%1,%2,%3};"
        : "+f"(c[0]), "+f"(c[1]), "+f"(c[2]), "+f"(c[3])
        : "r"(a[0]), "r"(a[1]), "r"(a[2]), "r"(a[3]), "r"(b[0]), "r"(b[1]));
}
__device__ __forceinline__ void cpa16(uint32_t dst, const void* src, int srcSize) {
    asm volatile("cp.async.cg.shared.global [%0], [%1], 16, %2;"
        :: "r"(dst), "l"(src), "r"(srcSize));
}
__device__ __forceinline__ void cp_commit() {
    asm volatile("cp.async.commit_group;" ::: "memory");
}
__device__ __forceinline__ void cp_wait0() {
    asm volatile("cp.async.wait_group 0;" ::: "memory");
}
__device__ __forceinline__ void split2(float v, __nv_bfloat16* hi, __nv_bfloat16* lo) {
    __nv_bfloat16 h = __float2bfloat16(v);
    *hi = h;
    *lo = __float2bfloat16(v - __bfloat162float(h));
}

// ---- fused weight prep: 14 segments covering rows [0, W_DEC) ----
struct PrepSeg { const float* src; int stride; int dst; int pad; };
struct PrepTab { PrepSeg s[NSEG]; };

__global__ void prep_all(PrepTab tab)
{
    int idx = blockIdx.x * blockDim.x + threadIdx.x;
    if (idx >= W_DEC * KPAD) return;
    int r = idx / KPAD, k = idx - r * KPAD;
    int si = 0;
    #pragma unroll
    for (int i = 1; i < NSEG; i++) if (r >= tab.s[i].dst) si = i;
    const PrepSeg sg = tab.s[si];
    int lr = r - sg.dst;
    float x = (k < FF) ? sg.src[(size_t)lr * sg.stride + k] : 0.f;
    split2(x, &g_wsp[(size_t)r * KPAD + k], &g_wsp[WPLANE + (size_t)r * KPAD + k]);
}

// decode rows 5200..5258
__global__ void prep_dec(const float* __restrict__ afw,
                         const float* __restrict__ bfw)
{
    int idx = blockIdx.x * blockDim.x + threadIdx.x;
    if (idx >= 59 * KPAD) return;
    int r = idx / KPAD, k = idx - r * KPAD;
    float x = 0.f;
    if (k < FF) {
        if (r < 39)      x = afw[(size_t)r * FF + k];
        else if (r < 49) x = bfw[(size_t)(r - 39) * (2 * FF) + k];
        else             x = bfw[(size_t)(r - 49) * (2 * FF) + FF + k];
    }
    size_t rr = (size_t)(W_DEC + r) * KPAD + k;
    split2(x, &g_wsp[rr], &g_wsp[WPLANE + rr]);
}

__global__ void split_molf(const float* __restrict__ src)
{
    int idx = blockIdx.x * blockDim.x + threadIdx.x;
    if (idx >= BB * KPAD) return;
    int r = idx / KPAD, k = idx - r * KPAD;
    float x = (k < FF) ? src[(size_t)r * FF + k] : 0.f;
    split2(x, &g_mfsp[idx], &g_mfsp[MPLANE + idx]);
}

__global__ void prep_misc(const float* __restrict__ ab, const float* __restrict__ bb,
                          const float* __restrict__ align_b, const float* __restrict__ attend_b)
{
    int i = blockIdx.x * blockDim.x + threadIdx.x;
    if (i < 64) {
        float v = 0.f;
        if (i < 39) v = ab[i];
        else if (i < 49) v = bb[i - 39];
        g_decb[i] = v;
    }
    int j = i - 64;
    if (j >= 0 && j < RROUNDS * F3) {
        int d = j / F3, f = j - d * F3;
        float v = 0.f;
        if (f < 200) v = align_b[d * FF + f];
        else if (f >= 400) v = attend_b[d * FF + f - 400];
        g_rb[j] = v;
    }
}

// ---- split-bf16 tensor GEMM ----
#define PITCH 80
#define REG 10240
#define STG 40960
#define TG_SMEM (2*STG)

template<int ACT, int OUT>
__global__ __launch_bounds__(256, 2) void tgemm(
    const __nv_bfloat16* __restrict__ Ap, const __nv_bfloat16* __restrict__ Wp,
    const float* __restrict__ bias, float* __restrict__ C,
    __nv_bfloat16* __restrict__ Cp,
    int M, int Nn, const float* __restrict__ rowAdd, int rpg,
    long aOffB, long wOffB, long cOffE)
{
    extern __shared__ __align__(16) char sm[];
    const uint32_t sb = smem_u32(sm);
    const int tid = threadIdx.x, lane = tid & 31, wid = tid >> 5;
    const int bm = blockIdx.y * 128, bn = blockIdx.x * 128;
    const int wm = (wid & 3) * 32, wn = (wid >> 2) * 64;

    float acc[2][8][4];
    #pragma unroll
    for (int i = 0; i < 2; i++)
        #pragma unroll
        for (int j = 0; j < 8; j++)
            #pragma unroll
            for (int k = 0; k < 4; k++) acc[i][j][k] = 0.f;

    const int r0 = tid >> 2, q0 = (tid & 3) * 16;
    const int r1 = r0 + 64;
    const int n0 = bn + r0, n1 = bn + r1;
    const int v0 = (n0 < Nn) ? 16 : 0, v1 = (n1 < Nn) ? 16 : 0;
    const char* pA0 = (const char*)(Ap + (size_t)(bm + r0) * KPAD) + q0;
    const char* pA1 = (const char*)(Ap + (size_t)(bm + r1) * KPAD) + q0;
    const char* pB0 = (const char*)(Wp + (size_t)(v0 ? n0 : 0) * KPAD) + q0;
    const char* pB1 = (const char*)(Wp + (size_t)(v1 ? n1 : 0) * KPAD) + q0;
    const uint32_t d0 = (uint32_t)(r0 * PITCH) + q0;
    const uint32_t d1 = (uint32_t)(r1 * PITCH) + q0;

    auto stage_load = [&](int t, int st) {
        const int kb = t * 64;
        const uint32_t s = sb + st * STG;
        cpa16(s + d0,         pA0 + kb, 16);
        cpa16(s + d1,         pA1 + kb, 16);
        cpa16(s + REG + d0,   pA0 + aOffB + kb, 16);
        cpa16(s + REG + d1,   pA1 + aOffB + kb, 16);
        cpa16(s + 2*REG + d0, pB0 + kb, v0);
        cpa16(s + 2*REG + d1, pB1 + kb, v1);
        cpa16(s + 3*REG + d0, pB0 + wOffB + kb, v0);
        cpa16(s + 3*REG + d1, pB1 + wOffB + kb, v1);
    };

    stage_load(0, 0);
    cp_commit();

    const int arow = lane & 15;
    const int brow = lane & 7, sel = lane >> 3;
    const int nOff = (sel >> 1) * 8, kOff = (sel & 1) * 8;

    for (int t = 0; t < NCH; t++) {
        cp_wait0();
        __syncthreads();
        if (t + 1 < NCH) { stage_load(t + 1, (t + 1) & 1); cp_commit(); }
        const uint32_t s = sb + (t & 1) * STG;

        #pragma unroll
        for (int ks = 0; ks < 32; ks += 16) {
            uint32_t ah[2][4], al[2][4];
            const uint32_t akc = (uint32_t)(ks + ((lane >> 4) << 3)) * 2;
            #pragma unroll
            for (int mi = 0; mi < 2; mi++) {
                uint32_t ad = s + (uint32_t)(wm + mi * 16 + arow) * PITCH + akc;
                ldsm4(ah[mi], ad);
                ldsm4(al[mi], ad + REG);
            }
            #pragma unroll
            for (int half = 0; half < 2; half++) {
                uint32_t bh[2][4], blo[2][4];
                #pragma unroll
                for (int p = 0; p < 2; p++) {
                    uint32_t bd = s + 2*REG
                        + (uint32_t)(wn + (half * 2 + p) * 16 + nOff + brow) * PITCH
                        + (uint32_t)(ks + kOff) * 2;
                    ldsm4(bh[p], bd);
                    ldsm4(blo[p], bd + REG);
                }
                #pragma unroll
                for (int mi = 0; mi < 2; mi++)
                    #pragma unroll
                    for (int nj = 0; nj < 4; nj++) {
                        const uint32_t* b2h = &bh[nj >> 1][(nj & 1) * 2];
                        const uint32_t* b2l = &blo[nj >> 1][(nj & 1) * 2];
                        float* a = acc[mi][half * 4 + nj];
                        mma_bf16(a, ah[mi], b2h);
                        mma_bf16(a, ah[mi], b2l);
                        mma_bf16(a, al[mi], b2h);
                    }
            }
        }
        __syncthreads();
    }

    const int lr = lane >> 2, lc = (lane & 3) * 2;
    #pragma unroll
    for (int mi = 0; mi < 2; mi++) {
        #pragma unroll
        for (int hh = 0; hh < 2; hh++) {
            int m = bm + wm + mi * 16 + hh * 8 + lr;
            const float* ra = rowAdd ? (rowAdd + (size_t)(m / rpg) * Nn) : nullptr;
            #pragma unroll
            for (int ni = 0; ni < 8; ni++) {
                int n = bn + wn + ni * 8 + lc;
                if (n >= Nn) continue;
                float v0f = acc[mi][ni][hh * 2 + 0];
                float v1f = acc[mi][ni][hh * 2 + 1];
                if (bias) { v0f += bias[n]; v1f += bias[n + 1]; }
                if (ra)   { v0f += ra[n];   v1f += ra[n + 1]; }
                if (ACT == 1) { v0f = (v0f > 0.f) ? v0f : expm1f(v0f);
                                v1f = (v1f > 0.f) ? v1f : expm1f(v1f); }
                else if (ACT == 2) { v0f = fmaxf(v0f, 0.f); v1f = fmaxf(v1f, 0.f); }
                if (OUT == 0) {
                    *(float2*)&C[(size_t)m * Nn + n] = make_float2(v0f, v1f);
                } else {
                    __nv_bfloat162 h2 = __floats2bfloat162_rn(v0f, v1f);
                    __nv_bfloat162 l2 = __floats2bfloat162_rn(
                        v0f - __bfloat162float(h2.x), v1f - __bfloat162float(h2.y));
                    size_t ci = (size_t)m * KPAD + n;
                    *(__nv_bfloat162*)&Cp[ci] = h2;
                    *(__nv_bfloat162*)&Cp[cOffE + ci] = l2;
                }
            }
        }
    }
}

__global__ __launch_bounds__(256) void mol_pre_kernel(
    const float* __restrict__ molf, const float* __restrict__ actf)
{
    int b = blockIdx.x;
    int tid = threadIdx.x;
    __shared__ float dots[LL];
    __shared__ float red[16];
    const float* mf = molf + (size_t)b * FF;
    int lane = tid & 31, warp = tid >> 5;

    for (int l = warp; l < LL; l += 8) {
        const float* af = actf + ((size_t)b * LL + l) * FF;
        float s = 0.f;
        for (int f = lane; f < FF; f += 32) s += mf[f] * af[f];
        #pragma unroll
        for (int o = 16; o > 0; o >>= 1) s += __shfl_xor_sync(0xffffffffu, s, o);
        if (lane == 0) dots[l] = s;
    }
    __syncthreads();

    float v = dots[tid];
    float m = v;
    #pragma unroll
    for (int o = 16; o > 0; o >>= 1) m = fmaxf(m, __shfl_xor_sync(0xffffffffu, m, o));
    if (lane == 0) red[warp] = m;
    __syncthreads();
    float mx = red[0];
    #pragma unroll
    for (int i = 1; i < 8; i++) mx = fmaxf(mx, red[i]);
    float e = expf(v - mx);
    float s = e;
    #pragma unroll
    for (int o = 16; o > 0; o >>= 1) s += __shfl_xor_sync(0xffffffffu, s, o);
    if (lane == 0) red[8 + warp] = s;
    __syncthreads();
    float tot = 0.f;
    #pragma unroll
    for (int i = 0; i < 8; i++) tot += red[8 + i];
    __syncthreads();
    dots[tid] = e / tot;
    __syncthreads();

    size_t base = (size_t)b * LL * FF;
    for (int i = tid; i < LL * FF; i += 256) {
        int l = i / FF, f = i - l * FF;
        float v2 = dots[l] * mf[f] + actf[base + i];
        size_t si = ((size_t)b * LL + l) * KPAD + f;
        split2(v2, &g_hsp[si], &g_hsp[APLANE + si]);
    }
}

__global__ __launch_bounds__(256) void gru_combine_kernel(
    const float* __restrict__ gi, const float* __restrict__ gh,
    const __nv_bfloat16* __restrict__ hsp, int writeH, int total)
{
    int idx = blockIdx.x * blockDim.x + threadIdx.x;
    if (idx >= total) return;
    int m = idx / FF, f = idx - m * FF;
    size_t b3 = (size_t)m * F3;
    float ir = gi[b3 + f], iz = gi[b3 + FF + f], in_ = gi[b3 + 2 * FF + f];
    float hr = gh[b3 + f], hz = gh[b3 + FF + f], hn = gh[b3 + 2 * FF + f];
    float r = 1.f / (1.f + expf(-(ir + hr)));
    float z = 1.f / (1.f + expf(-(iz + hz)));
    float n = tanhf(in_ + r * hn);
    size_t si = (size_t)m * KPAD + f;
    float h = __bfloat162float(hsp[si]) + __bfloat162float(hsp[APLANE + si]);
    float o = (1.f - z) * n + z * h;
    if (writeH) split2(o, &g_hsp[si], &g_hsp[APLANE + si]);
    float a = fmaxf(o, 0.f);
    split2(a, &g_asp[si], &g_asp[APLANE + si]);
}

__global__ __launch_bounds__(256) void attn_ctx_kernel(
    const float* __restrict__ sst, const int* __restrict__ deg)
{
    int bl = blockIdx.x;
    int b = bl >> 8;
    int tid = threadIdx.x;
    __shared__ int sidx[NNB];
    if (tid < NNB) sidx[tid] = deg[(size_t)bl * NNB + tid];
    __syncthreads();
    if (tid >= FF) return;
    int f = tid;
    float s1v = sst[(size_t)bl * F3 + f];
    float sc[NNB];
    float mx = -3.4e38f;
    #pragma unroll
    for (int n = 0; n < NNB; n++) {
        int j = sidx[n];
        float v = s1v + sst[((size_t)b * LL + j) * F3 + 200 + f];
        v = (v >= 0.f) ? v : 0.01f * v;
        if (j == LL - 1) v += -9e8f;
        sc[n] = v;
        mx = fmaxf(mx, v);
    }
    float sum = 0.f;
    #pragma unroll
    for (int n = 0; n < NNB; n++) { sc[n] = expf(sc[n] - mx); sum += sc[n]; }
    float inv = 1.f / sum;
    float c = 0.f;
    #pragma unroll
    for (int n = 0; n < NNB; n++) {
        int j = sidx[n];
        if (j != LL - 1)
            c += sc[n] * inv * sst[((size_t)b * LL + j) * F3 + 400 + f];
    }
    c = (c > 0.f) ? c : expm1f(c);
    size_t si = (size_t)bl * KPAD + f;
    split2(c, &g_csp[si], &g_csp[APLANE + si]);
}

__device__ __forceinline__ void seg_softmax_acc(const float* v, float* y, int lo, int hi) {
    float m = -3.4e38f;
    for (int i = lo; i < hi; i++) m = fmaxf(m, v[i]);
    float s = 0.f;
    for (int i = lo; i < hi; i++) s += expf(v[i] - m);
    float inv = 1.f / s;
    for (int i = lo; i < hi; i++) y[i] += expf(v[i] - m) * inv;
}
__device__ __forceinline__ float sigf(float x) { return 1.f / (1.f + expf(-x)); }

__global__ __launch_bounds__(256) void atom_act_kernel(
    const float* __restrict__ dec, float* __restrict__ out, int rows)
{
    int m = blockIdx.x * blockDim.x + threadIdx.x;
    if (m >= rows) return;
    const float* x = dec + (size_t)m * 64;
    float v[39], y[39];
    #pragma unroll
    for (int i = 0; i < 39; i++) { v[i] = x[i]; y[i] = 0.f; }
    seg_softmax_acc(v, y, 0, 16);
    seg_softmax_acc(v, y, 16, 22);
    seg_softmax_acc(v, y, 24, 30);
    seg_softmax_acc(v, y, 31, 36);
    y[24] += fmaxf(v[24], 0.f);
    y[30] += sigf(v[30]);
    y[36] += sigf(v[36]);
    y[37] += sigf(v[37]);
    y[38] += sigf(v[38]);
    float* o = out + (size_t)m * 39;
    #pragma unroll
    for (int i = 0; i < 39; i++) o[i] = y[i];
}

__global__ __launch_bounds__(256) void bond_act_kernel(
    const float* __restrict__ dec, const int* __restrict__ deg,
    float* __restrict__ out, int total)
{
    int id = blockIdx.x * blockDim.x + threadIdx.x;
    if (id >= total) return;
    int bl = id / NNB;
    int b = bl >> 8;
    int j = deg[id];
    const float* a = dec + (size_t)bl * 64 + 39;
    const float* c = dec + ((size_t)b * LL + j) * 64 + 49;
    float v[10], y[10];
    #pragma unroll
    for (int k = 0; k < 10; k++) { v[k] = a[k] + c[k]; y[k] = 0.f; }
    seg_softmax_acc(v, y, 0, 4);
    seg_softmax_acc(v, y, 6, 10);
    y[4] += sigf(v[4]);
    y[5] += sigf(v[5]);
    float* o = out + (size_t)id * 10;
    #pragma unroll
    for (int k = 0; k < 10; k++) o[k] = y[k];
}

static inline dim3 tg_grid(int M, int N) {
    return dim3((N + 127) / 128, M / 128);
}

extern "C" void kernel_launch(void* const* d_in, const int* in_sizes, int n_in,
                              void* d_out, int out_size)
{
    const int*   deg        = (const int*)  d_in[2];
    const float* molf       = (const float*)d_in[5];
    const float* actf       = (const float*)d_in[6];
    const float* atom_fc_w  = (const float*)d_in[7];
    const float* atom_fc_b  = (const float*)d_in[8];
    const float* bond_fc_w  = (const float*)d_in[9];
    const float* bond_fc_b  = (const float*)d_in[10];
    const float* align_w    = (const float*)d_in[11];
    const float* align_b    = (const float*)d_in[12];
    const float* attend_w   = (const float*)d_in[13];
    const float* attend_b   = (const float*)d_in[14];
    const float* gru_wih    = (const float*)d_in[15];
    const float* gru_whh    = (const float*)d_in[16];
    const float* gru_bih    = (const float*)d_in[17];
    const float* gru_bhh    = (const float*)d_in[18];
    const float* mol_al_w   = (const float*)d_in[19];
    const float* mol_al_b   = (const float*)d_in[20];
    const float* mgru_wih   = (const float*)d_in[21];
    const float* mgru_whh   = (const float*)d_in[22];
    const float* mgru_bih   = (const float*)d_in[23];
    const float* mgru_bhh   = (const float*)d_in[24];
    float* out = (float*)d_out;

    float *p_molW, *p_sst, *p_gi, *p_gh, *p_dec, *p_decb, *p_rb;
    __nv_bfloat16 *p_w, *p_h, *p_a, *p_c, *p_mf;
    cudaGetSymbolAddress((void**)&p_molW, g_molW);
    cudaGetSymbolAddress((void**)&p_sst,  g_sst);
    cudaGetSymbolAddress((void**)&p_gi,   g_gi);
    cudaGetSymbolAddress((void**)&p_gh,   g_gh);
    cudaGetSymbolAddress((void**)&p_dec,  g_dec);
    cudaGetSymbolAddress((void**)&p_decb, g_decb);
    cudaGetSymbolAddress((void**)&p_rb,   g_rb);
    cudaGetSymbolAddress((void**)&p_w,    g_wsp);
    cudaGetSymbolAddress((void**)&p_h,    g_hsp);
    cudaGetSymbolAddress((void**)&p_a,    g_asp);
    cudaGetSymbolAddress((void**)&p_c,    g_csp);
    cudaGetSymbolAddress((void**)&p_mf,   g_mfsp);

    cudaFuncSetAttribute(tgemm<0,0>, cudaFuncAttributeMaxDynamicSharedMemorySize, TG_SMEM);
    cudaFuncSetAttribute(tgemm<1,1>, cudaFuncAttributeMaxDynamicSharedMemorySize, TG_SMEM);

    const long AOB = (long)(APLANE * 2);
    const long MOB = (long)(MPLANE * 2);
    const long WOB = (long)(WPLANE * 2);

    {
        PrepTab tab;
        int i = 0;
        auto add = [&](const float* s, int st, int dst) {
            tab.s[i].src = s; tab.s[i].stride = st; tab.s[i].dst = dst; tab.s[i].pad = 0; i++;
        };
        add(mol_al_w,      2*FF, W_MOL0);
        add(mol_al_w + FF, 2*FF, W_MOL1);
        add(mgru_wih,      FF,   W_MGI);
        add(mgru_whh,      FF,   W_MGH);
        for (int d = 0; d < RROUNDS; d++) {
            const float* aw = align_w + (size_t)d * FF * 2 * FF;
            add(aw,                             2*FF, W_RND(d) + 0);
            add(aw + FF,                        2*FF, W_RND(d) + 200);
            add(attend_w + (size_t)d * FF * FF, FF,   W_RND(d) + 400);
            add(gru_wih + (size_t)d * F3 * FF,  FF,   W_RND(d) + 600);
            add(gru_whh + (size_t)d * F3 * FF,  FF,   W_RND(d) + 1200);
        }
        prep_all<<<(W_DEC * KPAD + 255) / 256, 256>>>(tab);
    }
    prep_dec<<<(59 * KPAD + 255) / 256, 256>>>(atom_fc_w, bond_fc_w);
    prep_misc<<<(64 + RROUNDS * F3 + 255) / 256, 256>>>(atom_fc_b, bond_fc_b, align_b, attend_b);
    split_molf<<<(BB * KPAD + 255) / 256, 256>>>(molf);

    #define WOFFP(o) (p_w + (size_t)(o) * KPAD)

    mol_pre_kernel<<<BB, 256>>>(molf, actf);

    tgemm<0,0><<<tg_grid(BB, FF), 256, TG_SMEM>>>(
        p_mf, WOFFP(W_MOL0), mol_al_b, p_molW, nullptr,
        BB, FF, nullptr, 1, MOB, WOB, 0);

    for (int t = 0; t < TSTEPS; t++) {
        tgemm<1,1><<<tg_grid(BL, FF), 256, TG_SMEM>>>(
            p_h, WOFFP(W_MOL1), nullptr, nullptr, p_c,
            BL, FF, p_molW, LL, AOB, WOB, (long)APLANE);
        tgemm<0,0><<<tg_grid(BL, F3), 256, TG_SMEM>>>(
            p_c, WOFFP(W_MGI), mgru_bih, p_gi, nullptr,
            BL, F3, nullptr, 1, AOB, WOB, 0);
        tgemm<0,0><<<tg_grid(BL, F3), 256, TG_SMEM>>>(
            p_h, WOFFP(W_MGH), mgru_bhh, p_gh, nullptr,
            BL, F3, nullptr, 1, AOB, WOB, 0);
        gru_combine_kernel<<<(BL * FF + 255) / 256, 256>>>(p_gi, p_gh, p_h, 1, BL * FF);
    }

    for (int d = 0; d < RROUNDS; d++) {
        tgemm<0,0><<<tg_grid(BL, F3), 256, TG_SMEM>>>(
            p_a, WOFFP(W_RND(d)), p_rb + (size_t)d * F3, p_sst, nullptr,
            BL, F3, nullptr, 1, AOB, WOB, 0);
        attn_ctx_kernel<<<BL, 256>>>(p_sst, deg);
        tgemm<0,0><<<tg_grid(BL, F3), 256, TG_SMEM>>>(
            p_c, WOFFP(W_RND(d) + 600), gru_bih + (size_t)d * F3, p_gi, nullptr,
            BL, F3, nullptr, 1, AOB, WOB, 0);
        tgemm<0,0><<<tg_grid(BL, F3), 256, TG_SMEM>>>(
            p_a, WOFFP(W_RND(d) + 1200), gru_bhh + (size_t)d * F3, p_gh, nullptr,
            BL, F3, nullptr, 1, AOB, WOB, 0);
        gru_combine_kernel<<<(BL * FF + 255) / 256, 256>>>(p_gi, p_gh, p_a, 0, BL * FF);
    }

    tgemm<0,0><<<tg_grid(BL, 64), 256, TG_SMEM>>>(
        p_a, WOFFP(W_DEC), p_decb, p_dec, nullptr,
        BL, 64, nullptr, 1, AOB, WOB, 0);

    atom_act_kernel<<<(BL + 255) / 256, 256>>>(p_dec, out, BL);
    bond_act_kernel<<<(BL * NNB + 255) / 256, 256>>>(p_dec, deg,
                                                     out + (size_t)BL * 39, BL * NNB);
}